// round 2
// baseline (speedup 1.0000x reference)
#include <cuda_runtime.h>
#include <cuda_bf16.h>
#include <cstdio>

#define N_NODES 50000
#define N_EDGES 800000
#define DIM 64
#define N_GRAPHS 256
#define N_LAYERS 3
#define D3 (DIM * N_LAYERS)   // 192
#define NV (N_NODES * DIM)    // 3,200,000

// ---------------- scratch (device globals; no allocation allowed) ----------
__device__ __align__(16) float g_z [NV];   // h + agg  (scatter target)
__device__ __align__(16) float g_z2[NV];   // post-MLP, pre-BN
__device__ __align__(16) float g_h [NV];   // post-BN  (next layer input)
__device__ float g_stats[2 * DIM];         // [sum | sumsq]
__device__ float g_pooled[N_GRAPHS * D3];

// ---------------------------------------------------------------------------
__global__ void k_zero_small() {
    int i = blockIdx.x * blockDim.x + threadIdx.x;
    if (i < N_GRAPHS * D3) g_pooled[i] = 0.f;
}
__global__ void k_zero_stats() {
    int i = threadIdx.x;
    if (i < 2 * DIM) g_stats[i] = 0.f;
}

// copy layer input into scatter buffer (only needed for layer 0; layers 1,2
// get g_z written directly by k_bn)
__global__ void k_copy_x(const float* __restrict__ x) {
    int i = blockIdx.x * blockDim.x + threadIdx.x;
    if (i < NV / 4) ((float4*)g_z)[i] = ((const float4*)x)[i];
}

// edge scatter: g_z[dst] += h[src]   (16 lanes per edge, float4 each)
__global__ void k_scatter(const float* __restrict__ x,
                          const int* __restrict__ src,
                          const int* __restrict__ dst,
                          int use_x) {
    int gid = blockIdx.x * blockDim.x + threadIdx.x;
    int e = gid >> 4;
    if (e >= N_EDGES) return;
    int l = gid & 15;
    const float* h = use_x ? x : g_h;
    int s = src[e];
    int d = dst[e];
    float4 v = ((const float4*)(h + (size_t)s * DIM))[l];
    float* p = g_z + (size_t)d * DIM + l * 4;
    asm volatile("red.global.add.v4.f32 [%0], {%1,%2,%3,%4};"
                 :: "l"(p), "f"(v.x), "f"(v.y), "f"(v.z), "f"(v.w)
                 : "memory");
}

// z2 = relu( relu(z @ W1 + B1) @ W2 + B2 ), one node per thread
__global__ void __launch_bounds__(128) k_mlp(
        const float* __restrict__ W1, const float* __restrict__ B1,
        const float* __restrict__ W2, const float* __restrict__ B2) {
    __shared__ __align__(16) float sW[DIM * DIM];
    __shared__ float sB[DIM];
    int t = threadIdx.x;
    int node = blockIdx.x * 128 + t;
    bool act = node < N_NODES;

    for (int i = t; i < DIM * DIM; i += 128) sW[i] = W1[i];
    if (t < DIM) sB[t] = B1[t];
    __syncthreads();

    float zr[DIM];
    if (act) {
        const float4* zp = (const float4*)(g_z + (size_t)node * DIM);
#pragma unroll
        for (int k = 0; k < 16; k++) {
            float4 v = zp[k];
            zr[4*k] = v.x; zr[4*k+1] = v.y; zr[4*k+2] = v.z; zr[4*k+3] = v.w;
        }
    }

    float hid[DIM];
    if (act) {
#pragma unroll
        for (int j4 = 0; j4 < 16; j4++) {
            float a0 = sB[4*j4+0], a1 = sB[4*j4+1], a2 = sB[4*j4+2], a3 = sB[4*j4+3];
#pragma unroll
            for (int k = 0; k < DIM; k++) {
                float4 w = *(const float4*)&sW[k * DIM + 4*j4];
                float zv = zr[k];
                a0 += zv * w.x; a1 += zv * w.y; a2 += zv * w.z; a3 += zv * w.w;
            }
            hid[4*j4+0] = fmaxf(a0, 0.f);
            hid[4*j4+1] = fmaxf(a1, 0.f);
            hid[4*j4+2] = fmaxf(a2, 0.f);
            hid[4*j4+3] = fmaxf(a3, 0.f);
        }
    }
    __syncthreads();
    for (int i = t; i < DIM * DIM; i += 128) sW[i] = W2[i];
    if (t < DIM) sB[t] = B2[t];
    __syncthreads();

    if (act) {
        float4* op = (float4*)(g_z2 + (size_t)node * DIM);
#pragma unroll
        for (int j4 = 0; j4 < 16; j4++) {
            float a0 = sB[4*j4+0], a1 = sB[4*j4+1], a2 = sB[4*j4+2], a3 = sB[4*j4+3];
#pragma unroll
            for (int k = 0; k < DIM; k++) {
                float4 w = *(const float4*)&sW[k * DIM + 4*j4];
                float hv = hid[k];
                a0 += hv * w.x; a1 += hv * w.y; a2 += hv * w.z; a3 += hv * w.w;
            }
            op[j4] = make_float4(fmaxf(a0, 0.f), fmaxf(a1, 0.f),
                                 fmaxf(a2, 0.f), fmaxf(a3, 0.f));
        }
    }
}

// per-feature sum / sumsq over all nodes (coalesced; block-reduced; atomics)
__global__ void __launch_bounds__(256) k_stats() {
    int d  = threadIdx.x & 63;
    int rg = threadIdx.x >> 6;            // 0..3
    float s = 0.f, s2 = 0.f;
    for (int r = blockIdx.x * 4 + rg; r < N_NODES; r += gridDim.x * 4) {
        float v = g_z2[(size_t)r * DIM + d];
        s += v; s2 += v * v;
    }
    __shared__ float sh[2][256];
    sh[0][threadIdx.x] = s;
    sh[1][threadIdx.x] = s2;
    __syncthreads();
    if (threadIdx.x < 64) {
        float ts = sh[0][d] + sh[0][64+d] + sh[0][128+d] + sh[0][192+d];
        float t2 = sh[1][d] + sh[1][64+d] + sh[1][128+d] + sh[1][192+d];
        atomicAdd(&g_stats[d], ts);
        atomicAdd(&g_stats[DIM + d], t2);
    }
}

// BN apply + write next-layer input (g_h AND g_z) + pooled accumulation
__global__ void k_bn(const float* __restrict__ gamma,
                     const float* __restrict__ beta,
                     const int* __restrict__ batch,
                     int layerOff, int last) {
    int idx = blockIdx.x * blockDim.x + threadIdx.x;
    if (idx >= NV) return;
    int d = idx & 63;
    int node = idx >> 6;
    const float invN = 1.f / N_NODES;
    float mean = g_stats[d] * invN;
    float var  = fmaxf(g_stats[DIM + d] * invN - mean * mean, 0.f);
    float inv  = rsqrtf(var + 1e-5f);
    float v = (g_z2[idx] - mean) * inv * gamma[d] + beta[d];
    if (!last) { g_h[idx] = v; g_z[idx] = v; }   // g_z = seed for next scatter
    int g = batch[node];
    atomicAdd(&g_pooled[g * D3 + layerOff + d], v);
}

// out = relu(pooled @ PW1 + PB1) @ PW2 + PB2,  one graph per block
__global__ void __launch_bounds__(D3) k_final(
        const float* __restrict__ PW1, const float* __restrict__ PB1,
        const float* __restrict__ PW2, const float* __restrict__ PB2,
        float* __restrict__ out) {
    int g = blockIdx.x;
    int t = threadIdx.x;
    __shared__ float row[D3];
    __shared__ float hid[D3];
    row[t] = g_pooled[g * D3 + t];
    __syncthreads();
    float acc = PB1[t];
#pragma unroll 8
    for (int k = 0; k < D3; k++) acc += row[k] * PW1[k * D3 + t];
    hid[t] = fmaxf(acc, 0.f);
    __syncthreads();
    float a2 = PB2[t];
#pragma unroll 8
    for (int k = 0; k < D3; k++) a2 += hid[k] * PW2[k * D3 + t];
    out[g * D3 + t] = a2;
}

// ---------------------------------------------------------------------------
extern "C" void kernel_launch(void* const* d_in, const int* in_sizes, int n_in,
                              void* d_out, int out_size) {
    const float* x     = (const float*)d_in[0];
    const int*   ei    = (const int*)d_in[1];     // [2, N_EDGES] int32
    const int*   batch = (const int*)d_in[2];     // [N_NODES]    int32
    const float* W1 = (const float*)d_in[3];   // [3,64,64]
    const float* B1 = (const float*)d_in[4];
    const float* W2 = (const float*)d_in[5];
    const float* B2 = (const float*)d_in[6];
    const float* gamma = (const float*)d_in[7];
    const float* beta  = (const float*)d_in[8];
    const float* PW1 = (const float*)d_in[9];
    const float* PB1 = (const float*)d_in[10];
    const float* PW2 = (const float*)d_in[11];
    const float* PB2 = (const float*)d_in[12];
    float* out = (float*)d_out;

    const int* src = ei;
    const int* dst = ei + N_EDGES;

    k_zero_small<<<(N_GRAPHS * D3 + 255) / 256, 256>>>();
    k_copy_x<<<(NV / 4 + 255) / 256, 256>>>(x);   // g_z = x (layer 0 seed)

    for (int l = 0; l < N_LAYERS; l++) {
        k_scatter<<<(N_EDGES * 16 + 255) / 256, 256>>>(x, src, dst, l == 0);
        k_mlp<<<(N_NODES + 127) / 128, 128>>>(W1 + l * DIM * DIM, B1 + l * DIM,
                                              W2 + l * DIM * DIM, B2 + l * DIM);
        k_zero_stats<<<1, 128>>>();
        k_stats<<<256, 256>>>();
        k_bn<<<(NV + 255) / 256, 256>>>(gamma + l * DIM, beta + l * DIM,
                                        batch, l * DIM, l == N_LAYERS - 1);
    }
    k_final<<<N_GRAPHS, D3>>>(PW1, PB1, PW2, PB2, out);
}

// round 3
// speedup vs baseline: 1.4078x; 1.4078x over previous
#include <cuda_runtime.h>
#include <cuda_bf16.h>
#include <cstdio>

#define N_NODES 50000
#define N_EDGES 800000
#define DIM 64
#define N_GRAPHS 256
#define N_LAYERS 3
#define D3 (DIM * N_LAYERS)   // 192
#define NV (N_NODES * DIM)    // 3,200,000

#define ZT_STRIDE 132         // padded row stride for transposed tiles

// ---------------- scratch (device globals; no allocation allowed) ----------
__device__ __align__(16) float g_z [NV];   // h + agg  (scatter target)
__device__ __align__(16) float g_z2[NV];   // post-MLP, pre-BN
__device__ __align__(16) float g_h [NV];   // post-BN  (next layer input)
__device__ float g_stats[2 * DIM];         // [sum | sumsq]
__device__ float g_pooled[N_GRAPHS * D3];

// ---------------------------------------------------------------------------
__global__ void k_zero_small() {
    int i = blockIdx.x * blockDim.x + threadIdx.x;
    if (i < N_GRAPHS * D3) g_pooled[i] = 0.f;
}
__global__ void k_zero_stats() {
    int i = threadIdx.x;
    if (i < 2 * DIM) g_stats[i] = 0.f;
}

// copy layer input into scatter buffer (only needed for layer 0)
__global__ void k_copy_x(const float* __restrict__ x) {
    int i = blockIdx.x * blockDim.x + threadIdx.x;
    if (i < NV / 4) ((float4*)g_z)[i] = ((const float4*)x)[i];
}

// edge scatter: g_z[dst] += h[src]   (16 lanes per edge, float4 each)
__global__ void k_scatter(const float* __restrict__ x,
                          const int* __restrict__ src,
                          const int* __restrict__ dst,
                          int use_x) {
    int gid = blockIdx.x * blockDim.x + threadIdx.x;
    int e = gid >> 4;
    if (e >= N_EDGES) return;
    int l = gid & 15;
    const float* h = use_x ? x : g_h;
    int s = src[e];
    int d = dst[e];
    float4 v = ((const float4*)(h + (size_t)s * DIM))[l];
    float* p = g_z + (size_t)d * DIM + l * 4;
    asm volatile("red.global.add.v4.f32 [%0], {%1,%2,%3,%4};"
                 :: "l"(p), "f"(v.x), "f"(v.y), "f"(v.z), "f"(v.w)
                 : "memory");
}

// ---------------------------------------------------------------------------
// Tiled MLP: z2 = relu( relu(z @ W1 + B1) @ W2 + B2 )
// Block tile: 128 nodes x 64 features, 256 threads, thread tile 8x4.
// Also accumulates per-feature sum/sumsq of z2 into g_stats (fused BN stats).
__global__ void __launch_bounds__(256, 2) k_mlp(
        const float* __restrict__ W1, const float* __restrict__ B1,
        const float* __restrict__ W2, const float* __restrict__ B2) {
    extern __shared__ float smem[];
    float* sZT = smem;                        // [64][ZT_STRIDE] transposed input
    float* sW  = sZT + 64 * ZT_STRIDE;        // [64][64]
    float* sHT = sW + 64 * 64;                // [64][ZT_STRIDE] transposed hidden

    const int t  = threadIdx.x;
    const int tm = t & 15;        // node-group 0..15   (8 nodes each)
    const int tn = t >> 4;        // feat-group 0..15   (4 feats each)
    const int blockNode = blockIdx.x * 128;

    // ---- load W1 + z tile (transposed) ----
    for (int i = t; i < DIM * DIM; i += 256) sW[i] = W1[i];
    {
        int nLoc = t & 15;        // node within 16-node slab
        int f4   = t >> 4;        // float4 index 0..15
        for (int s = 0; s < 8; s++) {
            int m = s * 16 + nLoc;
            int node = blockNode + m;
            float4 v = make_float4(0.f, 0.f, 0.f, 0.f);
            if (node < N_NODES)
                v = ((const float4*)(g_z + (size_t)node * DIM))[f4];
            sZT[(4 * f4 + 0) * ZT_STRIDE + m] = v.x;
            sZT[(4 * f4 + 1) * ZT_STRIDE + m] = v.y;
            sZT[(4 * f4 + 2) * ZT_STRIDE + m] = v.z;
            sZT[(4 * f4 + 3) * ZT_STRIDE + m] = v.w;
        }
    }
    __syncthreads();

    // ---- GEMM1: hid = relu(z @ W1 + B1) ----
    float acc[8][4];
    {
        float b0 = B1[4 * tn + 0], b1 = B1[4 * tn + 1];
        float b2 = B1[4 * tn + 2], b3 = B1[4 * tn + 3];
#pragma unroll
        for (int i = 0; i < 8; i++) {
            acc[i][0] = b0; acc[i][1] = b1; acc[i][2] = b2; acc[i][3] = b3;
        }
    }
#pragma unroll 4
    for (int k = 0; k < DIM; k++) {
        float4 a0 = *(const float4*)&sZT[k * ZT_STRIDE + 8 * tm];
        float4 a1 = *(const float4*)&sZT[k * ZT_STRIDE + 8 * tm + 4];
        float4 b  = *(const float4*)&sW[k * DIM + 4 * tn];
        float av[8] = {a0.x, a0.y, a0.z, a0.w, a1.x, a1.y, a1.z, a1.w};
#pragma unroll
        for (int i = 0; i < 8; i++) {
            acc[i][0] += av[i] * b.x;
            acc[i][1] += av[i] * b.y;
            acc[i][2] += av[i] * b.z;
            acc[i][3] += av[i] * b.w;
        }
    }
    // relu -> store transposed hidden
#pragma unroll
    for (int i = 0; i < 8; i++) {
        int m = 8 * tm + i;
#pragma unroll
        for (int j = 0; j < 4; j++)
            sHT[(4 * tn + j) * ZT_STRIDE + m] = fmaxf(acc[i][j], 0.f);
    }
    __syncthreads();
    for (int i = t; i < DIM * DIM; i += 256) sW[i] = W2[i];
    __syncthreads();

    // ---- GEMM2: z2 = relu(hid @ W2 + B2) ----
    {
        float b0 = B2[4 * tn + 0], b1 = B2[4 * tn + 1];
        float b2 = B2[4 * tn + 2], b3 = B2[4 * tn + 3];
#pragma unroll
        for (int i = 0; i < 8; i++) {
            acc[i][0] = b0; acc[i][1] = b1; acc[i][2] = b2; acc[i][3] = b3;
        }
    }
#pragma unroll 4
    for (int k = 0; k < DIM; k++) {
        float4 a0 = *(const float4*)&sHT[k * ZT_STRIDE + 8 * tm];
        float4 a1 = *(const float4*)&sHT[k * ZT_STRIDE + 8 * tm + 4];
        float4 b  = *(const float4*)&sW[k * DIM + 4 * tn];
        float av[8] = {a0.x, a0.y, a0.z, a0.w, a1.x, a1.y, a1.z, a1.w};
#pragma unroll
        for (int i = 0; i < 8; i++) {
            acc[i][0] += av[i] * b.x;
            acc[i][1] += av[i] * b.y;
            acc[i][2] += av[i] * b.z;
            acc[i][3] += av[i] * b.w;
        }
    }

    // ---- epilogue: relu, write z2, accumulate BN stats ----
    float psum[4] = {0.f, 0.f, 0.f, 0.f};
    float psq [4] = {0.f, 0.f, 0.f, 0.f};
#pragma unroll
    for (int i = 0; i < 8; i++) {
        int node = blockNode + 8 * tm + i;
        float v0 = fmaxf(acc[i][0], 0.f);
        float v1 = fmaxf(acc[i][1], 0.f);
        float v2 = fmaxf(acc[i][2], 0.f);
        float v3 = fmaxf(acc[i][3], 0.f);
        if (node < N_NODES) {
            *(float4*)(g_z2 + (size_t)node * DIM + 4 * tn) =
                make_float4(v0, v1, v2, v3);
            psum[0] += v0; psum[1] += v1; psum[2] += v2; psum[3] += v3;
            psq[0] += v0 * v0; psq[1] += v1 * v1;
            psq[2] += v2 * v2; psq[3] += v3 * v3;
        }
    }
    // reduce over tm (lanes 0..15 within each half-warp share tn)
#pragma unroll
    for (int ofs = 1; ofs <= 8; ofs <<= 1) {
#pragma unroll
        for (int j = 0; j < 4; j++) {
            psum[j] += __shfl_xor_sync(0xffffffffu, psum[j], ofs);
            psq [j] += __shfl_xor_sync(0xffffffffu, psq [j], ofs);
        }
    }
    if (tm == 0) {
#pragma unroll
        for (int j = 0; j < 4; j++) {
            atomicAdd(&g_stats[4 * tn + j], psum[j]);
            atomicAdd(&g_stats[DIM + 4 * tn + j], psq[j]);
        }
    }
}

// ---------------------------------------------------------------------------
// BN apply + next-layer input + pooled accumulation (run-length compressed
// atomics; batch is sorted). Thread: fixed feature d, 8 consecutive nodes.
__global__ void __launch_bounds__(256) k_bn(
        const float* __restrict__ gamma,
        const float* __restrict__ beta,
        const int* __restrict__ batch,
        int layerOff, int last) {
    int t = blockIdx.x * blockDim.x + threadIdx.x;
    int d = t & 63;
    int nodeBase = (t >> 6) * 8;
    if (nodeBase >= N_NODES) return;

    const float invN = 1.f / N_NODES;
    float mean = g_stats[d] * invN;
    float var  = fmaxf(g_stats[DIM + d] * invN - mean * mean, 0.f);
    float scale = rsqrtf(var + 1e-5f) * gamma[d];
    float shift = beta[d] - mean * scale;

    int curG = batch[nodeBase];
    float poolAcc = 0.f;
#pragma unroll
    for (int i = 0; i < 8; i++) {
        int node = nodeBase + i;
        if (node >= N_NODES) break;
        size_t idx = (size_t)node * DIM + d;
        float v = g_z2[idx] * scale + shift;
        if (!last) { g_h[idx] = v; g_z[idx] = v; }
        int g = batch[node];
        if (g != curG) {
            atomicAdd(&g_pooled[curG * D3 + layerOff + d], poolAcc);
            poolAcc = 0.f;
            curG = g;
        }
        poolAcc += v;
    }
    atomicAdd(&g_pooled[curG * D3 + layerOff + d], poolAcc);
}

// out = relu(pooled @ PW1 + PB1) @ PW2 + PB2,  one graph per block
__global__ void __launch_bounds__(D3) k_final(
        const float* __restrict__ PW1, const float* __restrict__ PB1,
        const float* __restrict__ PW2, const float* __restrict__ PB2,
        float* __restrict__ out) {
    int g = blockIdx.x;
    int t = threadIdx.x;
    __shared__ float row[D3];
    __shared__ float hid[D3];
    row[t] = g_pooled[g * D3 + t];
    __syncthreads();
    float acc = PB1[t];
#pragma unroll 8
    for (int k = 0; k < D3; k++) acc += row[k] * PW1[k * D3 + t];
    hid[t] = fmaxf(acc, 0.f);
    __syncthreads();
    float a2 = PB2[t];
#pragma unroll 8
    for (int k = 0; k < D3; k++) a2 += hid[k] * PW2[k * D3 + t];
    out[g * D3 + t] = a2;
}

// ---------------------------------------------------------------------------
extern "C" void kernel_launch(void* const* d_in, const int* in_sizes, int n_in,
                              void* d_out, int out_size) {
    const float* x     = (const float*)d_in[0];
    const int*   ei    = (const int*)d_in[1];     // [2, N_EDGES] int32
    const int*   batch = (const int*)d_in[2];     // [N_NODES]    int32
    const float* W1 = (const float*)d_in[3];   // [3,64,64]
    const float* B1 = (const float*)d_in[4];
    const float* W2 = (const float*)d_in[5];
    const float* B2 = (const float*)d_in[6];
    const float* gamma = (const float*)d_in[7];
    const float* beta  = (const float*)d_in[8];
    const float* PW1 = (const float*)d_in[9];
    const float* PB1 = (const float*)d_in[10];
    const float* PW2 = (const float*)d_in[11];
    const float* PB2 = (const float*)d_in[12];
    float* out = (float*)d_out;

    const int* src = ei;
    const int* dst = ei + N_EDGES;

    const int mlpSmem = (64 * ZT_STRIDE + 64 * 64 + 64 * ZT_STRIDE) * 4;
    static int attrDone = 0;
    if (!attrDone) {
        cudaFuncSetAttribute(k_mlp, cudaFuncAttributeMaxDynamicSharedMemorySize,
                             mlpSmem);
        attrDone = 1;
    }

    k_zero_small<<<(N_GRAPHS * D3 + 255) / 256, 256>>>();
    k_copy_x<<<(NV / 4 + 255) / 256, 256>>>(x);   // g_z = x (layer 0 seed)

    const int bnThreads = 64 * ((N_NODES + 7) / 8);          // 400000
    const int bnBlocks  = (bnThreads + 255) / 256;

    for (int l = 0; l < N_LAYERS; l++) {
        k_scatter<<<(N_EDGES * 16 + 255) / 256, 256>>>(x, src, dst, l == 0);
        k_zero_stats<<<1, 128>>>();
        k_mlp<<<(N_NODES + 127) / 128, 256, mlpSmem>>>(
            W1 + l * DIM * DIM, B1 + l * DIM,
            W2 + l * DIM * DIM, B2 + l * DIM);
        k_bn<<<bnBlocks, 256>>>(gamma + l * DIM, beta + l * DIM,
                                batch, l * DIM, l == N_LAYERS - 1);
    }
    k_final<<<N_GRAPHS, D3>>>(PW1, PB1, PW2, PB2, out);
}

// round 6
// speedup vs baseline: 1.5173x; 1.0778x over previous
#include <cuda_runtime.h>
#include <cuda_bf16.h>
#include <cstdio>

#define N_NODES 50000
#define N_EDGES 800000
#define DIM 64
#define N_GRAPHS 256
#define N_LAYERS 3
#define D3 (DIM * N_LAYERS)   // 192
#define NV (N_NODES * DIM)    // 3,200,000

#define ZT_STRIDE 132         // padded row stride for transposed tiles
#define N_PAD 53248           // 13 * 4096, padded node count for scan

// ---------------- scratch (device globals; no allocation allowed) ----------
__device__ __align__(16) float g_z2[NV];      // post-MLP, pre-BN
__device__ __align__(16) float g_h [NV];      // post-BN (next layer input)
__device__ float g_stats[N_LAYERS * 2 * DIM]; // per-layer [sum | sumsq]
__device__ float g_pooled[N_GRAPHS * D3];

__device__ __align__(16) int g_cnt   [N_PAD]; // per-dst degree (histogram)
__device__ __align__(16) int g_part  [N_PAD]; // scan partials
__device__ int g_bsum[16];
__device__ int g_boff[16];
__device__ int g_rowptr[N_PAD];
__device__ int g_cursor[N_PAD];
__device__ int g_srcsorted[N_EDGES];

// ---------------------------------------------------------------------------
// zero everything that is accumulated into each call
__global__ void k_zero_all() {
    int i = blockIdx.x * blockDim.x + threadIdx.x;
    if (i < N_PAD) g_cnt[i] = 0;
    else if (i < N_PAD + N_LAYERS * 2 * DIM) g_stats[i - N_PAD] = 0.f;
    else if (i < N_PAD + N_LAYERS * 2 * DIM + N_GRAPHS * D3)
        g_pooled[i - N_PAD - N_LAYERS * 2 * DIM] = 0.f;
}

__global__ void k_hist(const int* __restrict__ dst) {
    int e = blockIdx.x * blockDim.x + threadIdx.x;
    if (e < N_EDGES) atomicAdd(&g_cnt[dst[e]], 1);
}

// block scan: 13 blocks x 1024 threads x 4 elems
__global__ void __launch_bounds__(1024) k_scan1() {
    int b = blockIdx.x, t = threadIdx.x;
    int base = b * 4096 + t * 4;
    int4 c = *(const int4*)&g_cnt[base];
    int s0 = c.x, s1 = s0 + c.y, s2 = s1 + c.z, s3 = s2 + c.w;
    int tot = s3;
    __shared__ int sh[1024];
    sh[t] = tot;
    __syncthreads();
    for (int o = 1; o < 1024; o <<= 1) {
        int v = (t >= o) ? sh[t - o] : 0;
        __syncthreads();
        sh[t] += v;
        __syncthreads();
    }
    int ex = sh[t] - tot;   // exclusive prefix of this thread's 4-group
    int4 outv = make_int4(ex, ex + s0, ex + s1, ex + s2);
    *(int4*)&g_part[base] = outv;
    if (t == 1023) g_bsum[b] = sh[1023];
}

__global__ void k_scan2(int nblocks) {
    if (threadIdx.x == 0) {
        int acc = 0;
        for (int i = 0; i < nblocks; i++) { g_boff[i] = acc; acc += g_bsum[i]; }
    }
}

__global__ void k_scan3() {
    int i = blockIdx.x * blockDim.x + threadIdx.x;
    if (i < N_PAD) {
        int r = g_part[i] + g_boff[i >> 12];
        g_rowptr[i] = r;
        g_cursor[i] = r;
    }
}

__global__ void k_permute(const int* __restrict__ src,
                          const int* __restrict__ dst) {
    int e = blockIdx.x * blockDim.x + threadIdx.x;
    if (e < N_EDGES) {
        int pos = atomicAdd(&g_cursor[dst[e]], 1);
        g_srcsorted[pos] = src[e];
    }
}

// ---------------------------------------------------------------------------
// Fused CSR-gather + MLP: z = h[node] + sum_{j->node} h[j];
// z2 = relu( relu(z @ W1 + B1) @ W2 + B2 ); accumulate per-feature stats.
// Block tile: 128 nodes x 64 features, 256 threads, thread tile 8x4.
__global__ void __launch_bounds__(256, 2) k_mlp(
        const float* __restrict__ xin, int use_x, int layer,
        const float* __restrict__ W1, const float* __restrict__ B1,
        const float* __restrict__ W2, const float* __restrict__ B2) {
    extern __shared__ float smem[];
    float* sZT = smem;                        // [64][ZT_STRIDE] transposed z
    float* sW  = sZT + 64 * ZT_STRIDE;        // [64][64]
    float* sHT = sW + 64 * 64;                // [64][ZT_STRIDE] transposed hidden

    const int t  = threadIdx.x;
    const int tm = t & 15;        // node-group (8 nodes each) in GEMM phase
    const int tn = t >> 4;        // feat-group (4 feats each)
    const int blockNode = blockIdx.x * 128;
    const float4* hin4 = use_x ? (const float4*)xin : (const float4*)g_h;
    float* stats = g_stats + layer * 2 * DIM;

    // ---- W1 load + CSR-gather of z tile (transposed into sZT) ----
    for (int i = t; i < DIM * DIM; i += 256) sW[i] = W1[i];
    {
        const int chunk = t & 15;          // float4 chunk 0..15
        const int mLoc  = t >> 4;          // node slot 0..15 per pass
#pragma unroll
        for (int i = 0; i < 8; i++) {
            int m = i * 16 + mLoc;
            int node = blockNode + m;
            float4 a = make_float4(0.f, 0.f, 0.f, 0.f);
            if (node < N_NODES) {
                a = hin4[(size_t)node * 16 + chunk];
                int beg = g_rowptr[node];
                int deg = g_cnt[node];
                int j = 0;
                for (; j + 1 < deg; j += 2) {
                    int s0 = g_srcsorted[beg + j];
                    int s1 = g_srcsorted[beg + j + 1];
                    float4 v0 = hin4[(size_t)s0 * 16 + chunk];
                    float4 v1 = hin4[(size_t)s1 * 16 + chunk];
                    a.x += v0.x + v1.x; a.y += v0.y + v1.y;
                    a.z += v0.z + v1.z; a.w += v0.w + v1.w;
                }
                if (j < deg) {
                    int s0 = g_srcsorted[beg + j];
                    float4 v0 = hin4[(size_t)s0 * 16 + chunk];
                    a.x += v0.x; a.y += v0.y; a.z += v0.z; a.w += v0.w;
                }
            }
            sZT[(4 * chunk + 0) * ZT_STRIDE + m] = a.x;
            sZT[(4 * chunk + 1) * ZT_STRIDE + m] = a.y;
            sZT[(4 * chunk + 2) * ZT_STRIDE + m] = a.z;
            sZT[(4 * chunk + 3) * ZT_STRIDE + m] = a.w;
        }
    }
    __syncthreads();

    // ---- GEMM1: hid = relu(z @ W1 + B1) ----
    float acc[8][4];
    {
        float b0 = B1[4 * tn + 0], b1 = B1[4 * tn + 1];
        float b2 = B1[4 * tn + 2], b3 = B1[4 * tn + 3];
#pragma unroll
        for (int i = 0; i < 8; i++) {
            acc[i][0] = b0; acc[i][1] = b1; acc[i][2] = b2; acc[i][3] = b3;
        }
    }
#pragma unroll 4
    for (int k = 0; k < DIM; k++) {
        float4 a0 = *(const float4*)&sZT[k * ZT_STRIDE + 8 * tm];
        float4 a1 = *(const float4*)&sZT[k * ZT_STRIDE + 8 * tm + 4];
        float4 b  = *(const float4*)&sW[k * DIM + 4 * tn];
        float av[8] = {a0.x, a0.y, a0.z, a0.w, a1.x, a1.y, a1.z, a1.w};
#pragma unroll
        for (int i = 0; i < 8; i++) {
            acc[i][0] += av[i] * b.x;
            acc[i][1] += av[i] * b.y;
            acc[i][2] += av[i] * b.z;
            acc[i][3] += av[i] * b.w;
        }
    }
#pragma unroll
    for (int i = 0; i < 8; i++) {
        int m = 8 * tm + i;
#pragma unroll
        for (int j = 0; j < 4; j++)
            sHT[(4 * tn + j) * ZT_STRIDE + m] = fmaxf(acc[i][j], 0.f);
    }
    __syncthreads();
    for (int i = t; i < DIM * DIM; i += 256) sW[i] = W2[i];
    __syncthreads();

    // ---- GEMM2: z2 = relu(hid @ W2 + B2) ----
    {
        float b0 = B2[4 * tn + 0], b1 = B2[4 * tn + 1];
        float b2 = B2[4 * tn + 2], b3 = B2[4 * tn + 3];
#pragma unroll
        for (int i = 0; i < 8; i++) {
            acc[i][0] = b0; acc[i][1] = b1; acc[i][2] = b2; acc[i][3] = b3;
        }
    }
#pragma unroll 4
    for (int k = 0; k < DIM; k++) {
        float4 a0 = *(const float4*)&sHT[k * ZT_STRIDE + 8 * tm];
        float4 a1 = *(const float4*)&sHT[k * ZT_STRIDE + 8 * tm + 4];
        float4 b  = *(const float4*)&sW[k * DIM + 4 * tn];
        float av[8] = {a0.x, a0.y, a0.z, a0.w, a1.x, a1.y, a1.z, a1.w};
#pragma unroll
        for (int i = 0; i < 8; i++) {
            acc[i][0] += av[i] * b.x;
            acc[i][1] += av[i] * b.y;
            acc[i][2] += av[i] * b.z;
            acc[i][3] += av[i] * b.w;
        }
    }

    // ---- epilogue: relu, write z2, accumulate BN stats ----
    float psum[4] = {0.f, 0.f, 0.f, 0.f};
    float psq [4] = {0.f, 0.f, 0.f, 0.f};
#pragma unroll
    for (int i = 0; i < 8; i++) {
        int node = blockNode + 8 * tm + i;
        float v0 = fmaxf(acc[i][0], 0.f);
        float v1 = fmaxf(acc[i][1], 0.f);
        float v2 = fmaxf(acc[i][2], 0.f);
        float v3 = fmaxf(acc[i][3], 0.f);
        if (node < N_NODES) {
            *(float4*)(g_z2 + (size_t)node * DIM + 4 * tn) =
                make_float4(v0, v1, v2, v3);
            psum[0] += v0; psum[1] += v1; psum[2] += v2; psum[3] += v3;
            psq[0] += v0 * v0; psq[1] += v1 * v1;
            psq[2] += v2 * v2; psq[3] += v3 * v3;
        }
    }
#pragma unroll
    for (int ofs = 1; ofs <= 8; ofs <<= 1) {
#pragma unroll
        for (int j = 0; j < 4; j++) {
            psum[j] += __shfl_xor_sync(0xffffffffu, psum[j], ofs);
            psq [j] += __shfl_xor_sync(0xffffffffu, psq [j], ofs);
        }
    }
    if (tm == 0) {
#pragma unroll
        for (int j = 0; j < 4; j++) {
            atomicAdd(&stats[4 * tn + j], psum[j]);
            atomicAdd(&stats[DIM + 4 * tn + j], psq[j]);
        }
    }
}

// ---------------------------------------------------------------------------
// BN apply + next-layer input + pooled accumulation (run-length atomics).
__global__ void __launch_bounds__(256) k_bn(
        const float* __restrict__ gamma,
        const float* __restrict__ beta,
        const int* __restrict__ batch,
        int layer, int last) {
    int t = blockIdx.x * blockDim.x + threadIdx.x;
    int d = t & 63;
    int nodeBase = (t >> 6) * 8;
    if (nodeBase >= N_NODES) return;
    const float* stats = g_stats + layer * 2 * DIM;
    int layerOff = layer * DIM;

    const float invN = 1.f / N_NODES;
    float mean = stats[d] * invN;
    float var  = fmaxf(stats[DIM + d] * invN - mean * mean, 0.f);
    float scale = rsqrtf(var + 1e-5f) * gamma[d];
    float shift = beta[d] - mean * scale;

    int curG = batch[nodeBase];
    float poolAcc = 0.f;
#pragma unroll
    for (int i = 0; i < 8; i++) {
        int node = nodeBase + i;
        if (node >= N_NODES) break;
        size_t idx = (size_t)node * DIM + d;
        float v = g_z2[idx] * scale + shift;
        if (!last) g_h[idx] = v;
        int g = batch[node];
        if (g != curG) {
            atomicAdd(&g_pooled[curG * D3 + layerOff + d], poolAcc);
            poolAcc = 0.f;
            curG = g;
        }
        poolAcc += v;
    }
    atomicAdd(&g_pooled[curG * D3 + layerOff + d], poolAcc);
}

// out = relu(pooled @ PW1 + PB1) @ PW2 + PB2,  one graph per block
__global__ void __launch_bounds__(D3) k_final(
        const float* __restrict__ PW1, const float* __restrict__ PB1,
        const float* __restrict__ PW2, const float* __restrict__ PB2,
        float* __restrict__ out) {
    int g = blockIdx.x;
    int t = threadIdx.x;
    __shared__ float row[D3];
    __shared__ float hid[D3];
    row[t] = g_pooled[g * D3 + t];
    __syncthreads();
    float acc = PB1[t];
#pragma unroll 8
    for (int k = 0; k < D3; k++) acc += row[k] * PW1[k * D3 + t];
    hid[t] = fmaxf(acc, 0.f);
    __syncthreads();
    float a2 = PB2[t];
#pragma unroll 8
    for (int k = 0; k < D3; k++) a2 += hid[k] * PW2[k * D3 + t];
    out[g * D3 + t] = a2;
}

// ---------------------------------------------------------------------------
extern "C" void kernel_launch(void* const* d_in, const int* in_sizes, int n_in,
                              void* d_out, int out_size) {
    const float* x     = (const float*)d_in[0];
    const int*   ei    = (const int*)d_in[1];     // [2, N_EDGES] int32
    const int*   batch = (const int*)d_in[2];     // [N_NODES]    int32
    const float* W1 = (const float*)d_in[3];   // [3,64,64]
    const float* B1 = (const float*)d_in[4];
    const float* W2 = (const float*)d_in[5];
    const float* B2 = (const float*)d_in[6];
    const float* gamma = (const float*)d_in[7];
    const float* beta  = (const float*)d_in[8];
    const float* PW1 = (const float*)d_in[9];
    const float* PB1 = (const float*)d_in[10];
    const float* PW2 = (const float*)d_in[11];
    const float* PB2 = (const float*)d_in[12];
    float* out = (float*)d_out;

    const int* src = ei;
    const int* dst = ei + N_EDGES;

    const int mlpSmem = (64 * ZT_STRIDE + 64 * 64 + 64 * ZT_STRIDE) * 4;
    static int attrDone = 0;
    if (!attrDone) {
        cudaFuncSetAttribute(k_mlp, cudaFuncAttributeMaxDynamicSharedMemorySize,
                             mlpSmem);
        attrDone = 1;
    }

    const int zeroTot = N_PAD + N_LAYERS * 2 * DIM + N_GRAPHS * D3;
    k_zero_all<<<(zeroTot + 255) / 256, 256>>>();
    k_hist<<<(N_EDGES + 255) / 256, 256>>>(dst);
    k_scan1<<<N_PAD / 4096, 1024>>>();
    k_scan2<<<1, 32>>>(N_PAD / 4096);
    k_scan3<<<(N_PAD + 255) / 256, 256>>>();
    k_permute<<<(N_EDGES + 255) / 256, 256>>>(src, dst);

    const int bnThreads = 64 * ((N_NODES + 7) / 8);
    const int bnBlocks  = (bnThreads + 255) / 256;

    for (int l = 0; l < N_LAYERS; l++) {
        k_mlp<<<(N_NODES + 127) / 128, 256, mlpSmem>>>(
            x, l == 0 ? 1 : 0, l,
            W1 + l * DIM * DIM, B1 + l * DIM,
            W2 + l * DIM * DIM, B2 + l * DIM);
        k_bn<<<bnBlocks, 256>>>(gamma + l * DIM, beta + l * DIM,
                                batch, l, l == N_LAYERS - 1);
    }
    k_final<<<N_GRAPHS, D3>>>(PW1, PB1, PW2, PB2, out);
}

// round 7
// speedup vs baseline: 1.6577x; 1.0925x over previous
#include <cuda_runtime.h>
#include <cuda_bf16.h>
#include <cstdio>

#define N_NODES 50000
#define N_EDGES 800000
#define DIM 64
#define N_GRAPHS 256
#define N_LAYERS 3
#define D3 (DIM * N_LAYERS)   // 192
#define NV (N_NODES * DIM)    // 3,200,000

#define ZT_STRIDE 132         // padded row stride for transposed tiles
#define N_PAD 53248           // 13 * 4096, padded node count for scan

// ---------------- scratch (device globals; no allocation allowed) ----------
__device__ __align__(16) float g_z [NV];      // aggregated input (h + sum nbrs)
__device__ __align__(16) float g_z2[NV];      // post-MLP, pre-BN
__device__ __align__(16) float g_h [NV];      // post-BN (next layer input)
__device__ float g_stats[N_LAYERS * 2 * DIM]; // per-layer [sum | sumsq]
__device__ float g_pooled[N_GRAPHS * D3];

__device__ __align__(16) int g_cnt   [N_PAD]; // per-dst degree (histogram)
__device__ __align__(16) int g_part  [N_PAD]; // scan partials
__device__ int g_bsum[16];
__device__ int g_boff[16];
__device__ int g_rowptr[N_PAD];
__device__ int g_cursor[N_PAD];
__device__ int g_srcsorted[N_EDGES];

// ---------------------------------------------------------------------------
__global__ void k_zero_all() {
    int i = blockIdx.x * blockDim.x + threadIdx.x;
    if (i < N_PAD) g_cnt[i] = 0;
    else if (i < N_PAD + N_LAYERS * 2 * DIM) g_stats[i - N_PAD] = 0.f;
    else if (i < N_PAD + N_LAYERS * 2 * DIM + N_GRAPHS * D3)
        g_pooled[i - N_PAD - N_LAYERS * 2 * DIM] = 0.f;
}

__global__ void k_hist(const int* __restrict__ dst) {
    int e = blockIdx.x * blockDim.x + threadIdx.x;
    if (e < N_EDGES) atomicAdd(&g_cnt[dst[e]], 1);
}

// block scan: 13 blocks x 1024 threads x 4 elems
__global__ void __launch_bounds__(1024) k_scan1() {
    int b = blockIdx.x, t = threadIdx.x;
    int base = b * 4096 + t * 4;
    int4 c = *(const int4*)&g_cnt[base];
    int s0 = c.x, s1 = s0 + c.y, s2 = s1 + c.z, s3 = s2 + c.w;
    int tot = s3;
    __shared__ int sh[1024];
    sh[t] = tot;
    __syncthreads();
    for (int o = 1; o < 1024; o <<= 1) {
        int v = (t >= o) ? sh[t - o] : 0;
        __syncthreads();
        sh[t] += v;
        __syncthreads();
    }
    int ex = sh[t] - tot;
    int4 outv = make_int4(ex, ex + s0, ex + s1, ex + s2);
    *(int4*)&g_part[base] = outv;
    if (t == 1023) g_bsum[b] = sh[1023];
}

__global__ void k_scan2(int nblocks) {
    if (threadIdx.x == 0) {
        int acc = 0;
        for (int i = 0; i < nblocks; i++) { g_boff[i] = acc; acc += g_bsum[i]; }
    }
}

__global__ void k_scan3() {
    int i = blockIdx.x * blockDim.x + threadIdx.x;
    if (i < N_PAD) {
        int r = g_part[i] + g_boff[i >> 12];
        g_rowptr[i] = r;
        g_cursor[i] = r;
    }
}

__global__ void k_permute(const int* __restrict__ src,
                          const int* __restrict__ dst) {
    int e = blockIdx.x * blockDim.x + threadIdx.x;
    if (e < N_EDGES) {
        int pos = atomicAdd(&g_cursor[dst[e]], 1);
        g_srcsorted[pos] = src[e];
    }
}

// ---------------------------------------------------------------------------
// CSR gather, high occupancy: thread = (node, float4 chunk).
// g_z[node] = h[node] + sum_{j->node} h[j]
__global__ void __launch_bounds__(256) k_gather(
        const float* __restrict__ xin, int use_x) {
    int gid = blockIdx.x * blockDim.x + threadIdx.x;
    int node = gid >> 4;
    int chunk = gid & 15;
    if (node >= N_NODES) return;
    const float4* __restrict__ hin4 =
        use_x ? (const float4*)xin : (const float4*)g_h;

    float4 a = hin4[(size_t)node * 16 + chunk];
    int beg = g_rowptr[node];
    int deg = g_cnt[node];
    int j = 0;
    for (; j + 4 <= deg; j += 4) {
        int s0 = g_srcsorted[beg + j + 0];
        int s1 = g_srcsorted[beg + j + 1];
        int s2 = g_srcsorted[beg + j + 2];
        int s3 = g_srcsorted[beg + j + 3];
        float4 v0 = hin4[(size_t)s0 * 16 + chunk];
        float4 v1 = hin4[(size_t)s1 * 16 + chunk];
        float4 v2 = hin4[(size_t)s2 * 16 + chunk];
        float4 v3 = hin4[(size_t)s3 * 16 + chunk];
        a.x += (v0.x + v1.x) + (v2.x + v3.x);
        a.y += (v0.y + v1.y) + (v2.y + v3.y);
        a.z += (v0.z + v1.z) + (v2.z + v3.z);
        a.w += (v0.w + v1.w) + (v2.w + v3.w);
    }
    for (; j < deg; j++) {
        int s0 = g_srcsorted[beg + j];
        float4 v0 = hin4[(size_t)s0 * 16 + chunk];
        a.x += v0.x; a.y += v0.y; a.z += v0.z; a.w += v0.w;
    }
    ((float4*)g_z)[(size_t)node * 16 + chunk] = a;
}

// ---------------------------------------------------------------------------
// Tiled MLP: z2 = relu( relu(z @ W1 + B1) @ W2 + B2 ) + fused BN stats.
// Block tile: 128 nodes x 64 features, 256 threads, thread tile 8x4.
__global__ void __launch_bounds__(256, 2) k_mlp(
        int layer,
        const float* __restrict__ W1, const float* __restrict__ B1,
        const float* __restrict__ W2, const float* __restrict__ B2) {
    extern __shared__ float smem[];
    float* sZT = smem;                        // [64][ZT_STRIDE] transposed z
    float* sW  = sZT + 64 * ZT_STRIDE;        // [64][64]
    float* sHT = sW + 64 * 64;                // [64][ZT_STRIDE] transposed hidden

    const int t  = threadIdx.x;
    const int tm = t & 15;
    const int tn = t >> 4;
    const int blockNode = blockIdx.x * 128;
    float* stats = g_stats + layer * 2 * DIM;

    for (int i = t; i < DIM * DIM; i += 256) sW[i] = W1[i];
    {
        int nLoc = t & 15;
        int f4   = t >> 4;
#pragma unroll
        for (int s = 0; s < 8; s++) {
            int m = s * 16 + nLoc;
            int node = blockNode + m;
            float4 v = make_float4(0.f, 0.f, 0.f, 0.f);
            if (node < N_NODES)
                v = ((const float4*)g_z)[(size_t)node * 16 + f4];
            sZT[(4 * f4 + 0) * ZT_STRIDE + m] = v.x;
            sZT[(4 * f4 + 1) * ZT_STRIDE + m] = v.y;
            sZT[(4 * f4 + 2) * ZT_STRIDE + m] = v.z;
            sZT[(4 * f4 + 3) * ZT_STRIDE + m] = v.w;
        }
    }
    __syncthreads();

    float acc[8][4];
    {
        float b0 = B1[4 * tn + 0], b1 = B1[4 * tn + 1];
        float b2 = B1[4 * tn + 2], b3 = B1[4 * tn + 3];
#pragma unroll
        for (int i = 0; i < 8; i++) {
            acc[i][0] = b0; acc[i][1] = b1; acc[i][2] = b2; acc[i][3] = b3;
        }
    }
#pragma unroll 4
    for (int k = 0; k < DIM; k++) {
        float4 a0 = *(const float4*)&sZT[k * ZT_STRIDE + 8 * tm];
        float4 a1 = *(const float4*)&sZT[k * ZT_STRIDE + 8 * tm + 4];
        float4 b  = *(const float4*)&sW[k * DIM + 4 * tn];
        float av[8] = {a0.x, a0.y, a0.z, a0.w, a1.x, a1.y, a1.z, a1.w};
#pragma unroll
        for (int i = 0; i < 8; i++) {
            acc[i][0] += av[i] * b.x;
            acc[i][1] += av[i] * b.y;
            acc[i][2] += av[i] * b.z;
            acc[i][3] += av[i] * b.w;
        }
    }
#pragma unroll
    for (int i = 0; i < 8; i++) {
        int m = 8 * tm + i;
#pragma unroll
        for (int j = 0; j < 4; j++)
            sHT[(4 * tn + j) * ZT_STRIDE + m] = fmaxf(acc[i][j], 0.f);
    }
    __syncthreads();
    for (int i = t; i < DIM * DIM; i += 256) sW[i] = W2[i];
    __syncthreads();

    {
        float b0 = B2[4 * tn + 0], b1 = B2[4 * tn + 1];
        float b2 = B2[4 * tn + 2], b3 = B2[4 * tn + 3];
#pragma unroll
        for (int i = 0; i < 8; i++) {
            acc[i][0] = b0; acc[i][1] = b1; acc[i][2] = b2; acc[i][3] = b3;
        }
    }
#pragma unroll 4
    for (int k = 0; k < DIM; k++) {
        float4 a0 = *(const float4*)&sHT[k * ZT_STRIDE + 8 * tm];
        float4 a1 = *(const float4*)&sHT[k * ZT_STRIDE + 8 * tm + 4];
        float4 b  = *(const float4*)&sW[k * DIM + 4 * tn];
        float av[8] = {a0.x, a0.y, a0.z, a0.w, a1.x, a1.y, a1.z, a1.w};
#pragma unroll
        for (int i = 0; i < 8; i++) {
            acc[i][0] += av[i] * b.x;
            acc[i][1] += av[i] * b.y;
            acc[i][2] += av[i] * b.z;
            acc[i][3] += av[i] * b.w;
        }
    }

    float psum[4] = {0.f, 0.f, 0.f, 0.f};
    float psq [4] = {0.f, 0.f, 0.f, 0.f};
#pragma unroll
    for (int i = 0; i < 8; i++) {
        int node = blockNode + 8 * tm + i;
        float v0 = fmaxf(acc[i][0], 0.f);
        float v1 = fmaxf(acc[i][1], 0.f);
        float v2 = fmaxf(acc[i][2], 0.f);
        float v3 = fmaxf(acc[i][3], 0.f);
        if (node < N_NODES) {
            *(float4*)(g_z2 + (size_t)node * DIM + 4 * tn) =
                make_float4(v0, v1, v2, v3);
            psum[0] += v0; psum[1] += v1; psum[2] += v2; psum[3] += v3;
            psq[0] += v0 * v0; psq[1] += v1 * v1;
            psq[2] += v2 * v2; psq[3] += v3 * v3;
        }
    }
#pragma unroll
    for (int ofs = 1; ofs <= 8; ofs <<= 1) {
#pragma unroll
        for (int j = 0; j < 4; j++) {
            psum[j] += __shfl_xor_sync(0xffffffffu, psum[j], ofs);
            psq [j] += __shfl_xor_sync(0xffffffffu, psq [j], ofs);
        }
    }
    if (tm == 0) {
#pragma unroll
        for (int j = 0; j < 4; j++) {
            atomicAdd(&stats[4 * tn + j], psum[j]);
            atomicAdd(&stats[DIM + 4 * tn + j], psq[j]);
        }
    }
}

// ---------------------------------------------------------------------------
// BN apply + next-layer input + pooled accumulation (run-length atomics).
__global__ void __launch_bounds__(256) k_bn(
        const float* __restrict__ gamma,
        const float* __restrict__ beta,
        const int* __restrict__ batch,
        int layer, int last) {
    int t = blockIdx.x * blockDim.x + threadIdx.x;
    int d = t & 63;
    int nodeBase = (t >> 6) * 8;
    if (nodeBase >= N_NODES) return;
    const float* stats = g_stats + layer * 2 * DIM;
    int layerOff = layer * DIM;

    const float invN = 1.f / N_NODES;
    float mean = stats[d] * invN;
    float var  = fmaxf(stats[DIM + d] * invN - mean * mean, 0.f);
    float scale = rsqrtf(var + 1e-5f) * gamma[d];
    float shift = beta[d] - mean * scale;

    int curG = batch[nodeBase];
    float poolAcc = 0.f;
#pragma unroll
    for (int i = 0; i < 8; i++) {
        int node = nodeBase + i;
        if (node >= N_NODES) break;
        size_t idx = (size_t)node * DIM + d;
        float v = g_z2[idx] * scale + shift;
        if (!last) g_h[idx] = v;
        int g = batch[node];
        if (g != curG) {
            atomicAdd(&g_pooled[curG * D3 + layerOff + d], poolAcc);
            poolAcc = 0.f;
            curG = g;
        }
        poolAcc += v;
    }
    atomicAdd(&g_pooled[curG * D3 + layerOff + d], poolAcc);
}

// out = relu(pooled @ PW1 + PB1) @ PW2 + PB2,  one graph per block
__global__ void __launch_bounds__(D3) k_final(
        const float* __restrict__ PW1, const float* __restrict__ PB1,
        const float* __restrict__ PW2, const float* __restrict__ PB2,
        float* __restrict__ out) {
    int g = blockIdx.x;
    int t = threadIdx.x;
    __shared__ float row[D3];
    __shared__ float hid[D3];
    row[t] = g_pooled[g * D3 + t];
    __syncthreads();
    float acc = PB1[t];
#pragma unroll 8
    for (int k = 0; k < D3; k++) acc += row[k] * PW1[k * D3 + t];
    hid[t] = fmaxf(acc, 0.f);
    __syncthreads();
    float a2 = PB2[t];
#pragma unroll 8
    for (int k = 0; k < D3; k++) a2 += hid[k] * PW2[k * D3 + t];
    out[g * D3 + t] = a2;
}

// ---------------------------------------------------------------------------
extern "C" void kernel_launch(void* const* d_in, const int* in_sizes, int n_in,
                              void* d_out, int out_size) {
    const float* x     = (const float*)d_in[0];
    const int*   ei    = (const int*)d_in[1];     // [2, N_EDGES] int32
    const int*   batch = (const int*)d_in[2];     // [N_NODES]    int32
    const float* W1 = (const float*)d_in[3];   // [3,64,64]
    const float* B1 = (const float*)d_in[4];
    const float* W2 = (const float*)d_in[5];
    const float* B2 = (const float*)d_in[6];
    const float* gamma = (const float*)d_in[7];
    const float* beta  = (const float*)d_in[8];
    const float* PW1 = (const float*)d_in[9];
    const float* PB1 = (const float*)d_in[10];
    const float* PW2 = (const float*)d_in[11];
    const float* PB2 = (const float*)d_in[12];
    float* out = (float*)d_out;

    const int* src = ei;
    const int* dst = ei + N_EDGES;

    const int mlpSmem = (64 * ZT_STRIDE + 64 * 64 + 64 * ZT_STRIDE) * 4;
    static int attrDone = 0;
    if (!attrDone) {
        cudaFuncSetAttribute(k_mlp, cudaFuncAttributeMaxDynamicSharedMemorySize,
                             mlpSmem);
        attrDone = 1;
    }

    const int zeroTot = N_PAD + N_LAYERS * 2 * DIM + N_GRAPHS * D3;
    k_zero_all<<<(zeroTot + 255) / 256, 256>>>();
    k_hist<<<(N_EDGES + 255) / 256, 256>>>(dst);
    k_scan1<<<N_PAD / 4096, 1024>>>();
    k_scan2<<<1, 32>>>(N_PAD / 4096);
    k_scan3<<<(N_PAD + 255) / 256, 256>>>();
    k_permute<<<(N_EDGES + 255) / 256, 256>>>(src, dst);

    const int gatherThreads = N_NODES * 16;
    const int bnThreads = 64 * ((N_NODES + 7) / 8);
    const int bnBlocks  = (bnThreads + 255) / 256;

    for (int l = 0; l < N_LAYERS; l++) {
        k_gather<<<(gatherThreads + 255) / 256, 256>>>(x, l == 0 ? 1 : 0);
        k_mlp<<<(N_NODES + 127) / 128, 256, mlpSmem>>>(
            l,
            W1 + l * DIM * DIM, B1 + l * DIM,
            W2 + l * DIM * DIM, B2 + l * DIM);
        k_bn<<<bnBlocks, 256>>>(gamma + l * DIM, beta + l * DIM,
                                batch, l, l == N_LAYERS - 1);
    }
    k_final<<<N_GRAPHS, D3>>>(PW1, PB1, PW2, PB2, out);
}